// round 6
// baseline (speedup 1.0000x reference)
#include <cuda_runtime.h>

#define W     512
#define HIMG  512
#define TX    256
#define TYO   64
#define RB    8
#define PITCH 276          // 5*276 % 32 == 4  -> conflict-free strided LDS.128
#define NT    256

__device__ float g_part[8192];

__device__ __forceinline__ float ssim_from(float s1, float s2, float spp, float stt, float spt)
{
    // ssim pre-multiplied by 121^4:
    // num = (2*S1*S2 + C1*n^2) * (2*(n*Spt - S1*S2) + C2*n^2)
    // den = (S1^2 + S2^2 + C1*n^2) * (n*(Spp+Stt) - (S1^2+S2^2) + C2*n^2)
    const float C1n2 = 1.4641f;    // 0.01^2 * 121^2
    const float C2n2 = 13.1769f;   // 0.03^2 * 121^2
    float t1  = s1 * s2;
    float A   = fmaf(2.f, t1, C1n2);
    float cov = fmaf(121.f, spt, -t1);
    float Bv  = fmaf(2.f, cov, C2n2);
    float num = A * Bv;
    float d   = fmaf(s1, s1, s2 * s2);
    float Cv  = d + C1n2;
    float E   = fmaf(121.f, spp + stt, C2n2 - d);
    float den = Cv * E;
    return __fdividef(num, den);
}

__device__ __forceinline__ void hsum8(const float* __restrict__ src, float* __restrict__ S)
{
    float4 A = *(const float4*)(src);
    float4 B = *(const float4*)(src + 4);
    float4 C = *(const float4*)(src + 8);
    float4 D = *(const float4*)(src + 12);
    float4 E = *(const float4*)(src + 16);
    float w[20] = {A.x, A.y, A.z, A.w, B.x, B.y, B.z, B.w,
                   C.x, C.y, C.z, C.w, D.x, D.y, D.z, D.w,
                   E.x, E.y, E.z, E.w};
    // pairwise init sum of w[0..10]
    float s = (((w[0] + w[1]) + (w[2] + w[3])) + ((w[4] + w[5]) + (w[6] + w[7])))
            + ((w[8] + w[9]) + w[10]);
    S[0] = s;
#pragma unroll
    for (int j = 1; j < 8; ++j) {
        s += w[j + 10] - w[j - 1];
        S[j] = s;
    }
}

__global__ __launch_bounds__(256, 2)
void ssim_main(const float* __restrict__ pred, const float* __restrict__ tgt)
{
    __shared__ float vq[RB][5][PITCH];
    __shared__ float red[NT];

    const int t     = threadIdx.x;
    const int x0    = blockIdx.x * TX;
    const int y0    = blockIdx.y * TYO;
    const int plane = blockIdx.z;
    const float* __restrict__ P = pred + (size_t)plane * (W * HIMG);
    const float* __restrict__ T = tgt  + (size_t)plane * (W * HIMG);

    // column ownership: thread t owns halo col t; threads 0..9 also own col 256+t
    const int  gx0  = x0 - 5 + t;
    const bool in0  = (gx0 >= 0) && (gx0 < W);
    const bool has2 = (t < (TX + 10 - NT));   // t < 10
    const int  gx1  = gx0 + NT;
    const bool in1  = has2 && (gx1 < W);

    float a0 = 0.f, a1 = 0.f, a2 = 0.f, a3 = 0.f, a4 = 0.f;
    float b0 = 0.f, b1 = 0.f, b2 = 0.f, b3 = 0.f, b4 = 0.f;

    // ---- warm-up: accumulate rows y0-5 .. y0+4 (zeros outside image) ----
#pragma unroll 1
    for (int i = 0; i < 10; ++i) {
        int  y   = y0 - 5 + i;
        bool yok = (y >= 0);
        if (yok && in0) {
            float p = P[y * W + gx0], q = T[y * W + gx0];
            a0 += p; a1 += q;
            a2 = fmaf(p, p, a2); a3 = fmaf(q, q, a3); a4 = fmaf(p, q, a4);
        }
        if (yok && in1) {
            float p = P[y * W + gx1], q = T[y * W + gx1];
            b0 += p; b1 += q;
            b2 = fmaf(p, p, b2); b3 = fmaf(q, q, b3); b4 = fmaf(p, q, b4);
        }
    }

    float acc = 0.f;
    const int rr  = t & 7;         // row within batch (horizontal phase)
    const int seg = t >> 3;        // 0..31
    const int xb  = seg * 8;       // output-local col base

#pragma unroll 1
    for (int b = 0; b < TYO / RB; ++b) {
        // ---- vertical: advance running sums over RB incoming rows ----
#pragma unroll 1
        for (int r = 0; r < RB; ++r) {
            int yin  = y0 + 5 + b * RB + r;
            int yold = yin - 11;                      // row leaving the window
            bool subok = (yold >= y0 - 5) && (yold >= 0);
            if (subok && in0) {
                float p = P[yold * W + gx0], q = T[yold * W + gx0];
                a0 -= p; a1 -= q;
                a2 = fmaf(-p, p, a2); a3 = fmaf(-q, q, a3); a4 = fmaf(-p, q, a4);
            }
            if (in0 && yin < HIMG) {
                float p = P[yin * W + gx0], q = T[yin * W + gx0];
                a0 += p; a1 += q;
                a2 = fmaf(p, p, a2); a3 = fmaf(q, q, a3); a4 = fmaf(p, q, a4);
            }
            vq[r][0][t] = a0; vq[r][1][t] = a1; vq[r][2][t] = a2;
            vq[r][3][t] = a3; vq[r][4][t] = a4;
            if (has2) {
                if (subok && in1) {
                    float p = P[yold * W + gx1], q = T[yold * W + gx1];
                    b0 -= p; b1 -= q;
                    b2 = fmaf(-p, p, b2); b3 = fmaf(-q, q, b3); b4 = fmaf(-p, q, b4);
                }
                if (in1 && yin < HIMG) {
                    float p = P[yin * W + gx1], q = T[yin * W + gx1];
                    b0 += p; b1 += q;
                    b2 = fmaf(p, p, b2); b3 = fmaf(q, q, b3); b4 = fmaf(p, q, b4);
                }
                vq[r][0][NT + t] = b0; vq[r][1][NT + t] = b1; vq[r][2][NT + t] = b2;
                vq[r][3][NT + t] = b3; vq[r][4][NT + t] = b4;
            }
        }
        __syncthreads();

        // ---- horizontal sliding window + ssim for RB output rows ----
        {
            float S0[8], S1[8], S2[8], S3[8], S4[8];
            hsum8(&vq[rr][0][xb], S0);
            hsum8(&vq[rr][1][xb], S1);
            hsum8(&vq[rr][2][xb], S2);
            hsum8(&vq[rr][3][xb], S3);
            hsum8(&vq[rr][4][xb], S4);
#pragma unroll
            for (int j = 0; j < 8; ++j)
                acc += ssim_from(S0[j], S1[j], S2[j], S3[j], S4[j]);
        }
        __syncthreads();
    }

    // ---- deterministic block reduction ----
    red[t] = acc;
    __syncthreads();
#pragma unroll
    for (int o = 128; o > 0; o >>= 1) {
        if (t < o) red[t] += red[t + o];
        __syncthreads();
    }
    if (t == 0) {
        int bid = blockIdx.x + 2 * (blockIdx.y + 8 * blockIdx.z);
        g_part[bid] = red[0];
    }
}

__global__ void ssim_finalize(float* __restrict__ out, int nblocks, double total_count)
{
    __shared__ double sred[256];
    int t = threadIdx.x;
    double s = 0.0;
    for (int i = t; i < nblocks; i += 256) s += (double)g_part[i];
    sred[t] = s;
    __syncthreads();
#pragma unroll
    for (int o = 128; o > 0; o >>= 1) {
        if (t < o) sred[t] += sred[t + o];
        __syncthreads();
    }
    if (t == 0) out[0] = (float)(1.0 - sred[0] / total_count);
}

extern "C" void kernel_launch(void* const* d_in, const int* in_sizes, int n_in,
                              void* d_out, int out_size)
{
    const float* pred = (const float*)d_in[0];
    const float* tgt  = (const float*)d_in[1];
    float* out = (float*)d_out;

    int n      = in_sizes[0];
    int planes = n >> 18;                 // n / (512*512)

    dim3 grid(W / TX, HIMG / TYO, planes);   // (2, 8, planes)
    ssim_main<<<grid, NT>>>(pred, tgt);
    ssim_finalize<<<1, 256>>>(out, (W / TX) * (HIMG / TYO) * planes, (double)n);
}

// round 7
// speedup vs baseline: 1.6789x; 1.6789x over previous
#include <cuda_runtime.h>

#define W     512
#define HIMG  512
#define TX    256
#define TYO   64
#define RB    8
#define PITCH 276          // 5*276 % 32 == 4  -> conflict-free strided LDS.128
#define NT    288          // 266 column-owner threads + horizontal uses 256
#define NCOL  (TX + 10)    // 266 columns incl. halo

__device__ float g_part[8192];
__device__ int   g_cnt = 0;

__device__ __forceinline__ float ssim_from(float s1, float s2, float spp, float stt, float spt)
{
    // ssim pre-multiplied by 121^4:
    const float C1n2 = 1.4641f;    // 0.01^2 * 121^2
    const float C2n2 = 13.1769f;   // 0.03^2 * 121^2
    float t1  = s1 * s2;
    float A   = fmaf(2.f, t1, C1n2);
    float cov = fmaf(121.f, spt, -t1);
    float Bv  = fmaf(2.f, cov, C2n2);
    float num = A * Bv;
    float d   = fmaf(s1, s1, s2 * s2);
    float Cv  = d + C1n2;
    float E   = fmaf(121.f, spp + stt, C2n2 - d);
    float den = Cv * E;
    return __fdividef(num, den);
}

__device__ __forceinline__ void hsum8(const float* __restrict__ src, float* __restrict__ S)
{
    float4 A = *(const float4*)(src);
    float4 B = *(const float4*)(src + 4);
    float4 C = *(const float4*)(src + 8);
    float4 D = *(const float4*)(src + 12);
    float4 E = *(const float4*)(src + 16);
    float w[20] = {A.x, A.y, A.z, A.w, B.x, B.y, B.z, B.w,
                   C.x, C.y, C.z, C.w, D.x, D.y, D.z, D.w,
                   E.x, E.y, E.z, E.w};
    float s = (((w[0] + w[1]) + (w[2] + w[3])) + ((w[4] + w[5]) + (w[6] + w[7])))
            + ((w[8] + w[9]) + w[10]);
    S[0] = s;
#pragma unroll
    for (int j = 1; j < 8; ++j) {
        s += w[j + 10] - w[j - 1];
        S[j] = s;
    }
}

__global__ __launch_bounds__(NT, 2)
void ssim_main(const float* __restrict__ pred, const float* __restrict__ tgt,
               float* __restrict__ out, int nblocks, double total_count)
{
    __shared__ float  vq[RB][5][PITCH];
    __shared__ float  red[256];
    __shared__ double dred[256];
    __shared__ int    isLast;

    const int t     = threadIdx.x;
    const int x0    = blockIdx.x * TX;
    const int y0    = blockIdx.y * TYO;
    const int plane = blockIdx.z;
    const float* __restrict__ P = pred + (size_t)plane * (W * HIMG);
    const float* __restrict__ T = tgt  + (size_t)plane * (W * HIMG);

    // one column per thread: thread t owns global col x0-5+t  (t < 266)
    const int  gx    = x0 - 5 + t;
    const bool colok = (t < NCOL) && (gx >= 0) && (gx < W);
    const int  ylo   = (y0 >= 5) ? (y0 - 5) : 0;   // first row ever added

    float a0 = 0.f, a1 = 0.f, a2 = 0.f, a3 = 0.f, a4 = 0.f;

    // ---- warm-up: rows y0-5 .. y0+4, loads batched for MLP ----
    {
        float wp[10], wq[10];
#pragma unroll
        for (int i = 0; i < 10; ++i) {
            int  y  = y0 - 5 + i;
            bool ok = colok && (y >= 0);
            wp[i] = ok ? __ldg(P + y * W + gx) : 0.f;
            wq[i] = ok ? __ldg(T + y * W + gx) : 0.f;
        }
#pragma unroll
        for (int i = 0; i < 10; ++i) {
            a0 += wp[i]; a1 += wq[i];
            a2 = fmaf(wp[i], wp[i], a2);
            a3 = fmaf(wq[i], wq[i], a3);
            a4 = fmaf(wp[i], wq[i], a4);
        }
    }

    // ---- prefetch batch 0 incoming rows (y0+5 .. y0+12) ----
    float cip[RB], ciq[RB];
#pragma unroll
    for (int r = 0; r < RB; ++r) {
        int  y  = y0 + 5 + r;
        bool ok = colok && (y < HIMG);
        cip[r] = ok ? __ldg(P + y * W + gx) : 0.f;
        ciq[r] = ok ? __ldg(T + y * W + gx) : 0.f;
    }

    float acc = 0.f;
    const int  rr  = t & 7;
    const int  xb  = (t >> 3) * 8;
    const bool hok = (t < 256);

#pragma unroll 1
    for (int b = 0; b < TYO / RB; ++b) {
        // ---- outgoing rows: batched loads, L1-resident (touched 11-16 rows ago) ----
        float op[RB], oq[RB];
        const int yob = y0 - 6 + b * RB;
#pragma unroll
        for (int r = 0; r < RB; ++r) {
            int  y  = yob + r;
            bool ok = colok && (y >= ylo);
            op[r] = ok ? __ldg(P + y * W + gx) : 0.f;
            oq[r] = ok ? __ldg(T + y * W + gx) : 0.f;
        }

        // ---- vertical running-sum update + store (pure ALU, no load deps) ----
#pragma unroll
        for (int r = 0; r < RB; ++r) {
            a0 += cip[r] - op[r];
            a1 += ciq[r] - oq[r];
            a2 = fmaf(cip[r], cip[r], fmaf(-op[r], op[r], a2));
            a3 = fmaf(ciq[r], ciq[r], fmaf(-oq[r], oq[r], a3));
            a4 = fmaf(cip[r], ciq[r], fmaf(-op[r], oq[r], a4));
            if (t < NCOL) {
                vq[r][0][t] = a0; vq[r][1][t] = a1; vq[r][2][t] = a2;
                vq[r][3][t] = a3; vq[r][4][t] = a4;
            }
        }
        __syncthreads();

        // ---- prefetch NEXT batch's incoming rows; latency hidden by horizontal ----
        const int yib = y0 + 13 + b * RB;
        const bool more = (b < TYO / RB - 1);
#pragma unroll
        for (int r = 0; r < RB; ++r) {
            int  y  = yib + r;
            bool ok = colok && more && (y < HIMG);
            cip[r] = ok ? __ldg(P + y * W + gx) : 0.f;
            ciq[r] = ok ? __ldg(T + y * W + gx) : 0.f;
        }

        // ---- horizontal sliding window + ssim for RB output rows ----
        if (hok) {
            float S0[8], S1[8], S2[8], S3[8], S4[8];
            hsum8(&vq[rr][0][xb], S0);
            hsum8(&vq[rr][1][xb], S1);
            hsum8(&vq[rr][2][xb], S2);
            hsum8(&vq[rr][3][xb], S3);
            hsum8(&vq[rr][4][xb], S4);
#pragma unroll
            for (int j = 0; j < 8; ++j)
                acc += ssim_from(S0[j], S1[j], S2[j], S3[j], S4[j]);
        }
        __syncthreads();
    }

    // ---- deterministic block reduction (t < 256 hold partials) ----
    if (hok) red[t] = acc;
    __syncthreads();
#pragma unroll
    for (int o = 128; o > 0; o >>= 1) {
        if (t < o) red[t] += red[t + o];
        __syncthreads();
    }
    if (t == 0) {
        int bid = blockIdx.x + 2 * (blockIdx.y + 8 * (int)blockIdx.z);
        g_part[bid] = red[0];
        __threadfence();
        int v = atomicAdd(&g_cnt, 1);
        isLast = (v == nblocks - 1) ? 1 : 0;
    }
    __syncthreads();

    // ---- last block finalizes: fixed-order double sum -> deterministic ----
    if (isLast) {
        if (t < 256) {
            volatile float* gp = g_part;
            double s = 0.0;
            for (int i = t; i < nblocks; i += 256) s += (double)gp[i];
            dred[t] = s;
        }
        __syncthreads();
#pragma unroll
        for (int o = 128; o > 0; o >>= 1) {
            if (t < o) dred[t] += dred[t + o];
            __syncthreads();
        }
        if (t == 0) {
            out[0] = (float)(1.0 - dred[0] / total_count);
            g_cnt  = 0;   // reset for next graph replay
        }
    }
}

extern "C" void kernel_launch(void* const* d_in, const int* in_sizes, int n_in,
                              void* d_out, int out_size)
{
    const float* pred = (const float*)d_in[0];
    const float* tgt  = (const float*)d_in[1];
    float* out = (float*)d_out;

    int n      = in_sizes[0];
    int planes = n >> 18;                       // n / (512*512)
    int nblk   = (W / TX) * (HIMG / TYO) * planes;

    dim3 grid(W / TX, HIMG / TYO, planes);      // (2, 8, planes)
    ssim_main<<<grid, NT>>>(pred, tgt, out, nblk, (double)n);
}